// round 3
// baseline (speedup 1.0000x reference)
#include <cuda_runtime.h>
#include <math.h>

#define BATCH 32
#define NQ 900
#define NT 300
#define NC 256

// Scratch (no cudaMalloc allowed): cost matrix transposed [b][t][q] for the LSA
// inner loop (coalesced over q), plus per-(b,q) softmax stats.
__device__ float g_costT[(size_t)BATCH * NT * NQ];   // 34.56 MB
__device__ float g_rowmax[BATCH * NQ];
__device__ float g_rowsum[BATCH * NQ];

// ---------------------------------------------------------------------------
// Kernel A: softmax stats (max + sum of exp) per (b,q) row of logits.
// One warp per row; 256 = 32 lanes x 8 values.
// ---------------------------------------------------------------------------
__global__ void softmax_stats_kernel(const float* __restrict__ logits) {
    int warp = (blockIdx.x * blockDim.x + threadIdx.x) >> 5;
    int lane = threadIdx.x & 31;
    if (warp >= BATCH * NQ) return;
    const float* row = logits + (size_t)warp * NC;
    float vals[8];
    float m = -INFINITY;
#pragma unroll
    for (int i = 0; i < 8; i++) {
        vals[i] = row[lane + 32 * i];
        m = fmaxf(m, vals[i]);
    }
#pragma unroll
    for (int o = 16; o > 0; o >>= 1)
        m = fmaxf(m, __shfl_xor_sync(0xffffffffu, m, o));
    float s = 0.0f;
#pragma unroll
    for (int i = 0; i < 8; i++) s += expf(vals[i] - m);
#pragma unroll
    for (int o = 16; o > 0; o >>= 1)
        s += __shfl_xor_sync(0xffffffffu, s, o);
    if (lane == 0) {
        g_rowmax[warp] = m;
        g_rowsum[warp] = s;
    }
}

// ---------------------------------------------------------------------------
// Kernel B: cost matrix. grid (q-tiles, t, b); writes g_costT[b][t][q] coalesced.
// ---------------------------------------------------------------------------
__global__ void cost_kernel(const float* __restrict__ logits,
                            const float* __restrict__ pboxes,
                            const float* __restrict__ pcutin,
                            const int*   __restrict__ tlabels,
                            const float* __restrict__ tboxes,
                            const float* __restrict__ tcutin) {
    int q = blockIdx.x * blockDim.x + threadIdx.x;
    int t = blockIdx.y;
    int b = blockIdx.z;
    if (q >= NQ) return;

    float4 pb = reinterpret_cast<const float4*>(pboxes)[b * NQ + q];
    float4 tb = reinterpret_cast<const float4*>(tboxes)[b * NT + t];
    int   lab = tlabels[b * NT + t];

    int rq = b * NQ + q;
    float logit = logits[(size_t)rq * NC + lab];
    float prob  = expf(logit - g_rowmax[rq]) / g_rowsum[rq];

    float l1 = fabsf(pb.x - tb.x) + fabsf(pb.y - tb.y) +
               fabsf(pb.z - tb.z) + fabsf(pb.w - tb.w);

    float area_p = (pb.z - pb.x) * (pb.w - pb.y);
    float area_t = (tb.z - tb.x) * (tb.w - tb.y);

    float ix = fmaxf(fminf(pb.z, tb.z) - fmaxf(pb.x, tb.x), 0.0f);
    float iy = fmaxf(fminf(pb.w, tb.w) - fmaxf(pb.y, tb.y), 0.0f);
    float inter = ix * iy;
    float uni   = area_p + area_t - inter;
    float iou   = inter / uni;

    float ex = fmaxf(fmaxf(pb.z, tb.z) - fminf(pb.x, tb.x), 0.0f);
    float ey = fmaxf(fmaxf(pb.w, tb.w) - fminf(pb.y, tb.y), 0.0f);
    float enc = ex * ey;
    float giou = iou - (enc - uni) / enc;

    float cc = fabsf(pcutin[b * NQ + q] - tcutin[b * NT + t]);

    float cost = 5.0f * l1 - prob - 2.0f * giou + 2.0f * cc;
    g_costT[((size_t)b * NT + t) * NQ + q] = cost;
}

// ---------------------------------------------------------------------------
// Kernel C: transpose g_costT [b][t][q] -> out Cmat [b][q][t] as float32.
// ---------------------------------------------------------------------------
__global__ void transpose_out_kernel(float* __restrict__ out) {
    __shared__ float tile[32][33];
    int b  = blockIdx.z;
    int q0 = blockIdx.x * 32;
    int t0 = blockIdx.y * 32;
    int tx = threadIdx.x, ty = threadIdx.y;

    int q = q0 + tx, t = t0 + ty;
    if (q < NQ && t < NT)
        tile[ty][tx] = g_costT[((size_t)b * NT + t) * NQ + q];
    __syncthreads();
    int q2 = q0 + ty, t2 = t0 + tx;
    if (q2 < NQ && t2 < NT)
        out[((size_t)b * NQ + q2) * NT + t2] = tile[tx][ty];
}

// ---------------------------------------------------------------------------
// Kernel D: Jonker-Volgenant LSA, one block per batch, 1024 threads.
// Rows = targets (n=300), cols = queries (m=900). Mirrors the reference
// numpy implementation exactly (float64 duals, first-index argmin ties).
// ---------------------------------------------------------------------------
#define LSA_M NQ
#define LSA_N NT

__global__ __launch_bounds__(1024, 1) void lsa_kernel(float* __restrict__ out) {
    int b = blockIdx.x;
    int tid = threadIdx.x;

    __shared__ double s_v[LSA_M + 1];
    __shared__ double s_minv[LSA_M + 1];
    __shared__ double s_u[LSA_N + 1];
    __shared__ int    s_p[LSA_M + 1];
    __shared__ int    s_way[LSA_M + 1];
    __shared__ unsigned char s_used[LSA_M + 1];
    __shared__ double s_delta, s_ui0;
    __shared__ int s_j0, s_i0, s_j1, s_done;
    __shared__ double red_val[32];
    __shared__ int    red_idx[32];

    const float* cost = g_costT + (size_t)b * LSA_N * LSA_M;

    for (int j = tid; j <= LSA_M; j += 1024) { s_v[j] = 0.0; s_p[j] = 0; }
    for (int i = tid; i <= LSA_N; i += 1024) s_u[i] = 0.0;
    __syncthreads();

    for (int i = 1; i <= LSA_N; i++) {
        if (tid == 0) { s_p[0] = i; s_j0 = 0; }
        for (int j = tid; j <= LSA_M; j += 1024) { s_minv[j] = INFINITY; s_used[j] = 0; }
        __syncthreads();

        while (true) {
            // --- mark j0 used, broadcast i0, u[i0] ---
            if (tid == 0) {
                int j0 = s_j0;
                s_used[j0] = 1;
                int i0 = s_p[j0];
                s_i0 = i0;
                s_ui0 = s_u[i0];
            }
            __syncthreads();

            int    i0  = s_i0;
            double ui0 = s_ui0;
            int    j0  = s_j0;
            const float* crow = cost + (size_t)(i0 - 1) * LSA_M;

            // --- update minv over free columns; form argmin candidate ---
            double myval = INFINITY;
            int    myidx = LSA_M + 1;
            int j = tid;  // columns 1..900 handled by tid 1..900
            if (j >= 1 && j <= LSA_M && !s_used[j]) {
                double cur = (double)crow[j - 1] - ui0 - s_v[j];
                if (cur < s_minv[j]) { s_minv[j] = cur; s_way[j] = j0; }
                myval = s_minv[j];
                myidx = j;
            }

            // --- block argmin (value, smallest index on tie) ---
#pragma unroll
            for (int o = 16; o > 0; o >>= 1) {
                double ov = __shfl_down_sync(0xffffffffu, myval, o);
                int    oi = __shfl_down_sync(0xffffffffu, myidx, o);
                if (ov < myval || (ov == myval && oi < myidx)) { myval = ov; myidx = oi; }
            }
            int wid = tid >> 5, lane = tid & 31;
            if (lane == 0) { red_val[wid] = myval; red_idx[wid] = myidx; }
            __syncthreads();
            if (wid == 0) {
                myval = red_val[lane];
                myidx = red_idx[lane];
#pragma unroll
                for (int o = 16; o > 0; o >>= 1) {
                    double ov = __shfl_down_sync(0xffffffffu, myval, o);
                    int    oi = __shfl_down_sync(0xffffffffu, myidx, o);
                    if (ov < myval || (ov == myval && oi < myidx)) { myval = ov; myidx = oi; }
                }
                if (lane == 0) { s_delta = myval; s_j1 = myidx; }
            }
            __syncthreads();

            double delta = s_delta;
            int    j1    = s_j1;

            // --- dual update (used rows/cols distinct -> race-free) ---
            if (j <= LSA_M) {
                if (s_used[j]) {
                    s_u[s_p[j]] += delta;
                    s_v[j]      -= delta;
                } else {
                    s_minv[j]   -= delta;
                }
            }
            // tid 0 advances the path head in the same barrier interval: s_j0 is
            // only *read* by other threads after the barrier below, and the new
            // s_used marking happens after the next iteration's first barrier.
            if (tid == 0) {
                s_j0 = j1;
                s_done = (s_p[j1] == 0);
            }
            __syncthreads();
            if (s_done) break;
        }

        // --- augment along parent pointers (short, sequential) ---
        if (tid == 0) {
            int j0 = s_j0;
            while (j0) {
                int jp = s_way[j0];
                s_p[j0] = s_p[jp];
                j0 = jp;
            }
        }
        __syncthreads();
    }

    // --- emit q_idx (assigned query per target) and t_idx as float32 ---
    float* qout = out + (size_t)BATCH * NQ * NT + (size_t)b * NT;
    float* tout = out + (size_t)BATCH * NQ * NT + (size_t)BATCH * NT + (size_t)b * NT;
    for (int j = tid + 1; j <= LSA_M; j += 1024) {
        int pi = s_p[j];
        if (pi > 0) qout[pi - 1] = (float)(j - 1);
    }
    for (int t = tid; t < NT; t += 1024) tout[t] = (float)t;
}

// ---------------------------------------------------------------------------
extern "C" void kernel_launch(void* const* d_in, const int* in_sizes, int n_in,
                              void* d_out, int out_size) {
    const float* logits  = (const float*)d_in[0];
    const float* pboxes  = (const float*)d_in[1];
    const float* pcutin  = (const float*)d_in[2];
    const int*   tlabels = (const int*)  d_in[3];
    const float* tboxes  = (const float*)d_in[4];
    const float* tcutin  = (const float*)d_in[5];
    float* out = (float*)d_out;

    int rows = BATCH * NQ;                       // 28800 warps
    softmax_stats_kernel<<<(rows * 32 + 255) / 256, 256>>>(logits);

    dim3 gB((NQ + 255) / 256, NT, BATCH);
    cost_kernel<<<gB, 256>>>(logits, pboxes, pcutin, tlabels, tboxes, tcutin);

    dim3 gT((NQ + 31) / 32, (NT + 31) / 32, BATCH);
    transpose_out_kernel<<<gT, dim3(32, 32)>>>(out);

    lsa_kernel<<<BATCH, 1024>>>(out);
}

// round 6
// speedup vs baseline: 1.1192x; 1.1192x over previous
#include <cuda_runtime.h>
#include <math.h>
#include <limits.h>

#define BATCH 32
#define NQ 900
#define NT 300
#define NC 256

__device__ float g_costT[(size_t)BATCH * NT * NQ];   // 34.56 MB
__device__ float g_rowmax[BATCH * NQ];
__device__ float g_rowsum[BATCH * NQ];

// ---------------------------------------------------------------------------
// Kernel A: softmax stats (max + sum of exp) per (b,q) row of logits.
// ---------------------------------------------------------------------------
__global__ void softmax_stats_kernel(const float* __restrict__ logits) {
    int warp = (blockIdx.x * blockDim.x + threadIdx.x) >> 5;
    int lane = threadIdx.x & 31;
    if (warp >= BATCH * NQ) return;
    const float* row = logits + (size_t)warp * NC;
    float vals[8];
    float m = -INFINITY;
#pragma unroll
    for (int i = 0; i < 8; i++) {
        vals[i] = row[lane + 32 * i];
        m = fmaxf(m, vals[i]);
    }
#pragma unroll
    for (int o = 16; o > 0; o >>= 1)
        m = fmaxf(m, __shfl_xor_sync(0xffffffffu, m, o));
    float s = 0.0f;
#pragma unroll
    for (int i = 0; i < 8; i++) s += expf(vals[i] - m);
#pragma unroll
    for (int o = 16; o > 0; o >>= 1)
        s += __shfl_xor_sync(0xffffffffu, s, o);
    if (lane == 0) {
        g_rowmax[warp] = m;
        g_rowsum[warp] = s;
    }
}

// ---------------------------------------------------------------------------
// Kernel B: cost matrix -> g_costT[b][t][q] (coalesced in q).
// ---------------------------------------------------------------------------
__global__ void cost_kernel(const float* __restrict__ logits,
                            const float* __restrict__ pboxes,
                            const float* __restrict__ pcutin,
                            const int*   __restrict__ tlabels,
                            const float* __restrict__ tboxes,
                            const float* __restrict__ tcutin) {
    int q = blockIdx.x * blockDim.x + threadIdx.x;
    int t = blockIdx.y;
    int b = blockIdx.z;
    if (q >= NQ) return;

    float4 pb = reinterpret_cast<const float4*>(pboxes)[b * NQ + q];
    float4 tb = reinterpret_cast<const float4*>(tboxes)[b * NT + t];
    int   lab = tlabels[b * NT + t];

    int rq = b * NQ + q;
    float logit = logits[(size_t)rq * NC + lab];
    float prob  = expf(logit - g_rowmax[rq]) / g_rowsum[rq];

    float l1 = fabsf(pb.x - tb.x) + fabsf(pb.y - tb.y) +
               fabsf(pb.z - tb.z) + fabsf(pb.w - tb.w);

    float area_p = (pb.z - pb.x) * (pb.w - pb.y);
    float area_t = (tb.z - tb.x) * (tb.w - tb.y);

    float ix = fmaxf(fminf(pb.z, tb.z) - fmaxf(pb.x, tb.x), 0.0f);
    float iy = fmaxf(fminf(pb.w, tb.w) - fmaxf(pb.y, tb.y), 0.0f);
    float inter = ix * iy;
    float uni   = area_p + area_t - inter;
    float iou   = inter / uni;

    float ex = fmaxf(fmaxf(pb.z, tb.z) - fminf(pb.x, tb.x), 0.0f);
    float ey = fmaxf(fmaxf(pb.w, tb.w) - fminf(pb.y, tb.y), 0.0f);
    float enc = ex * ey;
    float giou = iou - (enc - uni) / enc;

    float cc = fabsf(pcutin[b * NQ + q] - tcutin[b * NT + t]);

    float cost = 5.0f * l1 - prob - 2.0f * giou + 2.0f * cc;
    g_costT[((size_t)b * NT + t) * NQ + q] = cost;
}

// ---------------------------------------------------------------------------
// Kernel C: transpose g_costT [b][t][q] -> out Cmat [b][q][t] (float32).
// ---------------------------------------------------------------------------
__global__ void transpose_out_kernel(float* __restrict__ out) {
    __shared__ float tile[32][33];
    int b  = blockIdx.z;
    int q0 = blockIdx.x * 32;
    int t0 = blockIdx.y * 32;
    int tx = threadIdx.x, ty = threadIdx.y;

    int q = q0 + tx, t = t0 + ty;
    if (q < NQ && t < NT)
        tile[ty][tx] = g_costT[((size_t)b * NT + t) * NQ + q];
    __syncthreads();
    int q2 = q0 + ty, t2 = t0 + tx;
    if (q2 < NQ && t2 < NT)
        out[((size_t)b * NQ + q2) * NT + t2] = tile[tx][ty];
}

// ---------------------------------------------------------------------------
// Kernel D: Jonker-Volgenant LSA. One block of 128 threads per batch; each
// thread owns 8 strided columns with register-resident v/minv/used state.
// ONE __syncthreads per Dijkstra step. Float64 dual arithmetic in the exact
// op order of the reference -> bit-identical assignments.
// ---------------------------------------------------------------------------
#define LSA_THREADS 128
#define LSA_K 8            // 128*8 = 1024 >= 900 columns

__global__ __launch_bounds__(LSA_THREADS, 1) void lsa_kernel(float* __restrict__ out) {
    int b   = blockIdx.x;
    int tid = threadIdx.x;
    int wid = tid >> 5, lane = tid & 31;

    __shared__ double s_u[NT + 1];
    __shared__ int    s_p[NQ + 1];
    __shared__ int    s_way[NQ + 1];
    __shared__ double s_rv[2][4];
    __shared__ int    s_ri[2][4];

    const float* cost = g_costT + (size_t)b * NT * NQ;

    for (int j = tid; j <= NQ; j += LSA_THREADS) s_p[j] = 0;
    for (int i = tid; i <= NT; i += LSA_THREADS) s_u[i] = 0.0;

    double v[LSA_K];
#pragma unroll
    for (int k = 0; k < LSA_K; k++) v[k] = 0.0;

    __syncthreads();

    int parity = 0;

    for (int i = 1; i <= NT; i++) {
        double minv[LSA_K];
        unsigned usedmask = 0;
#pragma unroll
        for (int k = 0; k < LSA_K; k++) minv[k] = INFINITY;

        int j0 = 0;

        while (true) {
            int    i0  = (j0 == 0) ? i : s_p[j0];
            double ui0 = s_u[i0];
            const float* crow = cost + (size_t)(i0 - 1) * NQ;

            // --- scan own columns: update minv/way, build local argmin ---
            double bval = INFINITY;
            int    bidx = INT_MAX;
#pragma unroll
            for (int k = 0; k < LSA_K; k++) {
                int j = 1 + tid + LSA_THREADS * k;
                if (j <= NQ && !((usedmask >> k) & 1u)) {
                    double cur = (double)__ldg(crow + (j - 1)) - ui0 - v[k];
                    if (cur < minv[k]) { minv[k] = cur; s_way[j] = j0; }
                    // k ascending => j ascending: strict < keeps smallest j on ties
                    if (minv[k] < bval) { bval = minv[k]; bidx = j; }
                }
            }

            // --- warp argmin (value, then smallest index) ---
#pragma unroll
            for (int o = 16; o > 0; o >>= 1) {
                double ov = __shfl_down_sync(0xffffffffu, bval, o);
                int    oi = __shfl_down_sync(0xffffffffu, bidx, o);
                if (ov < bval || (ov == bval && oi < bidx)) { bval = ov; bidx = oi; }
            }
            if (lane == 0) { s_rv[parity][wid] = bval; s_ri[parity][wid] = bidx; }

            __syncthreads();   // the ONLY barrier per step

            // --- every thread reduces the 4 per-warp results ---
            double delta = s_rv[parity][0];
            int    j1    = s_ri[parity][0];
#pragma unroll
            for (int w = 1; w < 4; w++) {
                double ov = s_rv[parity][w];
                int    oi = s_ri[parity][w];
                if (ov < delta || (ov == delta && oi < j1)) { delta = ov; j1 = oi; }
            }
            parity ^= 1;

            // --- dual update (register state + race-free s_u scatter) ---
            if (tid == 0) s_u[i] += delta;          // virtual column 0: p[0] = i
#pragma unroll
            for (int k = 0; k < LSA_K; k++) {
                int j = 1 + tid + LSA_THREADS * k;
                if (j <= NQ) {
                    if ((usedmask >> k) & 1u) {
                        v[k] -= delta;
                        s_u[s_p[j]] += delta;       // distinct rows across used cols
                    } else {
                        minv[k] -= delta;
                    }
                }
            }

            // mark j1 used (owner thread only; takes effect next scan)
            if (((j1 - 1) & (LSA_THREADS - 1)) == tid)
                usedmask |= 1u << ((j1 - 1) >> 7);

            int pj1 = s_p[j1];
            j0 = j1;
            if (pj1 == 0) break;
        }

        // --- augment along parent pointers ---
        __syncthreads();       // u-scatter reads of s_p finish before walk writes
        if (tid == 0) {
            int jj = j0;
            while (jj) {
                int jp = s_way[jj];
                s_p[jj] = (jp == 0) ? i : s_p[jp];
                jj = jp;
            }
        }
        __syncthreads();
    }

    // --- emit q_idx and t_idx as float32 ---
    float* qout = out + (size_t)BATCH * NQ * NT + (size_t)b * NT;
    float* tout = out + (size_t)BATCH * NQ * NT + (size_t)BATCH * NT + (size_t)b * NT;
    for (int j = tid + 1; j <= NQ; j += LSA_THREADS) {
        int pi = s_p[j];
        if (pi > 0) qout[pi - 1] = (float)(j - 1);
    }
    for (int t = tid; t < NT; t += LSA_THREADS) tout[t] = (float)t;
}

// ---------------------------------------------------------------------------
extern "C" void kernel_launch(void* const* d_in, const int* in_sizes, int n_in,
                              void* d_out, int out_size) {
    const float* logits  = (const float*)d_in[0];
    const float* pboxes  = (const float*)d_in[1];
    const float* pcutin  = (const float*)d_in[2];
    const int*   tlabels = (const int*)  d_in[3];
    const float* tboxes  = (const float*)d_in[4];
    const float* tcutin  = (const float*)d_in[5];
    float* out = (float*)d_out;

    int rows = BATCH * NQ;
    softmax_stats_kernel<<<(rows * 32 + 255) / 256, 256>>>(logits);

    dim3 gB((NQ + 255) / 256, NT, BATCH);
    cost_kernel<<<gB, 256>>>(logits, pboxes, pcutin, tlabels, tboxes, tcutin);

    dim3 gT((NQ + 31) / 32, (NT + 31) / 32, BATCH);
    transpose_out_kernel<<<gT, dim3(32, 32)>>>(out);

    lsa_kernel<<<BATCH, LSA_THREADS>>>(out);
}

// round 8
// speedup vs baseline: 2.6077x; 2.3301x over previous
#include <cuda_runtime.h>
#include <math.h>
#include <limits.h>

#define BATCH 32
#define NQ 900
#define NT 300
#define NC 256

__device__ float g_costT[(size_t)BATCH * NT * NQ];   // 34.56 MB
__device__ float g_rowmax[BATCH * NQ];
__device__ float g_rowsum[BATCH * NQ];

// ---------------------------------------------------------------------------
// Kernel A: softmax stats (max + sum of exp) per (b,q) row of logits.
// ---------------------------------------------------------------------------
__global__ void softmax_stats_kernel(const float* __restrict__ logits) {
    int warp = (blockIdx.x * blockDim.x + threadIdx.x) >> 5;
    int lane = threadIdx.x & 31;
    if (warp >= BATCH * NQ) return;
    const float* row = logits + (size_t)warp * NC;
    float vals[8];
    float m = -INFINITY;
#pragma unroll
    for (int i = 0; i < 8; i++) {
        vals[i] = row[lane + 32 * i];
        m = fmaxf(m, vals[i]);
    }
#pragma unroll
    for (int o = 16; o > 0; o >>= 1)
        m = fmaxf(m, __shfl_xor_sync(0xffffffffu, m, o));
    float s = 0.0f;
#pragma unroll
    for (int i = 0; i < 8; i++) s += expf(vals[i] - m);
#pragma unroll
    for (int o = 16; o > 0; o >>= 1)
        s += __shfl_xor_sync(0xffffffffu, s, o);
    if (lane == 0) {
        g_rowmax[warp] = m;
        g_rowsum[warp] = s;
    }
}

// ---------------------------------------------------------------------------
// Kernel B: cost matrix -> g_costT[b][t][q] (coalesced in q).
// ---------------------------------------------------------------------------
__global__ void cost_kernel(const float* __restrict__ logits,
                            const float* __restrict__ pboxes,
                            const float* __restrict__ pcutin,
                            const int*   __restrict__ tlabels,
                            const float* __restrict__ tboxes,
                            const float* __restrict__ tcutin) {
    int q = blockIdx.x * blockDim.x + threadIdx.x;
    int t = blockIdx.y;
    int b = blockIdx.z;
    if (q >= NQ) return;

    float4 pb = reinterpret_cast<const float4*>(pboxes)[b * NQ + q];
    float4 tb = reinterpret_cast<const float4*>(tboxes)[b * NT + t];
    int   lab = tlabels[b * NT + t];

    int rq = b * NQ + q;
    float logit = logits[(size_t)rq * NC + lab];
    float prob  = expf(logit - g_rowmax[rq]) / g_rowsum[rq];

    float l1 = fabsf(pb.x - tb.x) + fabsf(pb.y - tb.y) +
               fabsf(pb.z - tb.z) + fabsf(pb.w - tb.w);

    float area_p = (pb.z - pb.x) * (pb.w - pb.y);
    float area_t = (tb.z - tb.x) * (tb.w - tb.y);

    float ix = fmaxf(fminf(pb.z, tb.z) - fmaxf(pb.x, tb.x), 0.0f);
    float iy = fmaxf(fminf(pb.w, tb.w) - fmaxf(pb.y, tb.y), 0.0f);
    float inter = ix * iy;
    float uni   = area_p + area_t - inter;
    float iou   = inter / uni;

    float ex = fmaxf(fmaxf(pb.z, tb.z) - fminf(pb.x, tb.x), 0.0f);
    float ey = fmaxf(fmaxf(pb.w, tb.w) - fminf(pb.y, tb.y), 0.0f);
    float enc = ex * ey;
    float giou = iou - (enc - uni) / enc;

    float cc = fabsf(pcutin[b * NQ + q] - tcutin[b * NT + t]);

    float cost = 5.0f * l1 - prob - 2.0f * giou + 2.0f * cc;
    g_costT[((size_t)b * NT + t) * NQ + q] = cost;
}

// ---------------------------------------------------------------------------
// Kernel C: transpose g_costT [b][t][q] -> out Cmat [b][q][t] (float32).
// ---------------------------------------------------------------------------
__global__ void transpose_out_kernel(float* __restrict__ out) {
    __shared__ float tile[32][33];
    int b  = blockIdx.z;
    int q0 = blockIdx.x * 32;
    int t0 = blockIdx.y * 32;
    int tx = threadIdx.x, ty = threadIdx.y;

    int q = q0 + tx, t = t0 + ty;
    if (q < NQ && t < NT)
        tile[ty][tx] = g_costT[((size_t)b * NT + t) * NQ + q];
    __syncthreads();
    int q2 = q0 + ty, t2 = t0 + tx;
    if (q2 < NQ && t2 < NT)
        out[((size_t)b * NQ + q2) * NT + t2] = tile[tx][ty];
}

// ---------------------------------------------------------------------------
// Kernel D: Jonker-Volgenant LSA with dual-feasible warm start.
//   Phase 0: u[i] = min_j cost[i][j] (v=0) -> dual feasible; greedy-assign
//            rows to their argmin column if free (~85% of rows).
//   Phase 1: successive-shortest-path augmentation (Dijkstra) for the
//            remaining rows. Exact float64 dual arithmetic; optimal matching
//            (identical to reference when the optimum is unique).
// 128 threads/block; per-thread register state for 8 strided columns; one
// __syncthreads per Dijkstra step.
// ---------------------------------------------------------------------------
#define LSA_THREADS 128
#define LSA_K 8            // 128*8 = 1024 >= 900 columns

__global__ __launch_bounds__(LSA_THREADS, 1) void lsa_kernel(float* __restrict__ out) {
    int b   = blockIdx.x;
    int tid = threadIdx.x;
    int wid = tid >> 5, lane = tid & 31;

    __shared__ double s_u[NT + 1];
    __shared__ int    s_p[NQ + 1];
    __shared__ int    s_way[NQ + 1];
    __shared__ int    s_rowarg[NT + 1];
    __shared__ unsigned char s_skip[NT + 1];
    __shared__ double s_rv[2][4];
    __shared__ int    s_ri[2][4];

    const float* cost = g_costT + (size_t)b * NT * NQ;

    for (int j = tid; j <= NQ; j += LSA_THREADS) s_p[j] = 0;
    __syncthreads();

    // ---- Phase 0a: per-row minima (one warp per row, coalesced scan) ----
    for (int r = wid; r < NT; r += 4) {
        const float* crow = cost + (size_t)r * NQ;
        float bv = INFINITY;
        int   bj = INT_MAX;
        for (int j = lane; j < NQ; j += 32) {
            float c = __ldg(crow + j);
            if (c < bv) { bv = c; bj = j; }   // ascending j: strict < keeps smallest
        }
#pragma unroll
        for (int o = 16; o > 0; o >>= 1) {
            float ov = __shfl_down_sync(0xffffffffu, bv, o);
            int   oi = __shfl_down_sync(0xffffffffu, bj, o);
            if (ov < bv || (ov == bv && oi < bj)) { bv = ov; bj = oi; }
        }
        if (lane == 0) {
            s_u[r + 1]      = (double)bv;   // dual-feasible: u[i]+v[j] <= c
            s_rowarg[r + 1] = bj + 1;       // 1-based column
        }
    }
    __syncthreads();

    // ---- Phase 0b: greedy assignment on tight edges ----
    if (tid == 0) {
        s_u[0] = 0.0;
        for (int i = 1; i <= NT; i++) {
            int j = s_rowarg[i];
            if (s_p[j] == 0) { s_p[j] = i; s_skip[i] = 1; }
            else             { s_skip[i] = 0; }
        }
    }
    __syncthreads();

    double v[LSA_K];
#pragma unroll
    for (int k = 0; k < LSA_K; k++) v[k] = 0.0;

    int parity = 0;

    // ---- Phase 1: augment remaining rows ----
    for (int i = 1; i <= NT; i++) {
        if (s_skip[i]) continue;

        double minv[LSA_K];
        unsigned usedmask = 0;
#pragma unroll
        for (int k = 0; k < LSA_K; k++) minv[k] = INFINITY;

        int j0 = 0;

        while (true) {
            int    i0  = (j0 == 0) ? i : s_p[j0];
            double ui0 = s_u[i0];
            const float* crow = cost + (size_t)(i0 - 1) * NQ;

            // --- scan own columns: update minv/way, build local argmin ---
            double bval = INFINITY;
            int    bidx = INT_MAX;
#pragma unroll
            for (int k = 0; k < LSA_K; k++) {
                int j = 1 + tid + LSA_THREADS * k;
                if (j <= NQ && !((usedmask >> k) & 1u)) {
                    double cur = (double)__ldg(crow + (j - 1)) - ui0 - v[k];
                    if (cur < minv[k]) { minv[k] = cur; s_way[j] = j0; }
                    if (minv[k] < bval) { bval = minv[k]; bidx = j; }
                }
            }

            // --- warp argmin (value, then smallest index) ---
#pragma unroll
            for (int o = 16; o > 0; o >>= 1) {
                double ov = __shfl_down_sync(0xffffffffu, bval, o);
                int    oi = __shfl_down_sync(0xffffffffu, bidx, o);
                if (ov < bval || (ov == bval && oi < bidx)) { bval = ov; bidx = oi; }
            }
            if (lane == 0) { s_rv[parity][wid] = bval; s_ri[parity][wid] = bidx; }

            __syncthreads();   // the ONLY barrier per step

            // --- every thread reduces the 4 per-warp results ---
            double delta = s_rv[parity][0];
            int    j1    = s_ri[parity][0];
#pragma unroll
            for (int w = 1; w < 4; w++) {
                double ov = s_rv[parity][w];
                int    oi = s_ri[parity][w];
                if (ov < delta || (ov == delta && oi < j1)) { delta = ov; j1 = oi; }
            }
            parity ^= 1;

            // --- dual update (register state + race-free s_u scatter) ---
            if (tid == 0) s_u[i] += delta;          // virtual column 0: p[0] = i
#pragma unroll
            for (int k = 0; k < LSA_K; k++) {
                int j = 1 + tid + LSA_THREADS * k;
                if (j <= NQ) {
                    if ((usedmask >> k) & 1u) {
                        v[k] -= delta;
                        s_u[s_p[j]] += delta;       // distinct rows across used cols
                    } else {
                        minv[k] -= delta;
                    }
                }
            }

            // mark j1 used (owner thread only; takes effect next scan)
            if (((j1 - 1) & (LSA_THREADS - 1)) == tid)
                usedmask |= 1u << ((j1 - 1) >> 7);

            int pj1 = s_p[j1];
            j0 = j1;
            if (pj1 == 0) break;
        }

        // --- augment along parent pointers ---
        __syncthreads();       // u-scatter reads of s_p finish before walk writes
        if (tid == 0) {
            int jj = j0;
            while (jj) {
                int jp = s_way[jj];
                s_p[jj] = (jp == 0) ? i : s_p[jp];
                jj = jp;
            }
        }
        __syncthreads();
    }

    // --- emit q_idx and t_idx as float32 ---
    float* qout = out + (size_t)BATCH * NQ * NT + (size_t)b * NT;
    float* tout = out + (size_t)BATCH * NQ * NT + (size_t)BATCH * NT + (size_t)b * NT;
    for (int j = tid + 1; j <= NQ; j += LSA_THREADS) {
        int pi = s_p[j];
        if (pi > 0) qout[pi - 1] = (float)(j - 1);
    }
    for (int t = tid; t < NT; t += LSA_THREADS) tout[t] = (float)t;
}

// ---------------------------------------------------------------------------
extern "C" void kernel_launch(void* const* d_in, const int* in_sizes, int n_in,
                              void* d_out, int out_size) {
    const float* logits  = (const float*)d_in[0];
    const float* pboxes  = (const float*)d_in[1];
    const float* pcutin  = (const float*)d_in[2];
    const int*   tlabels = (const int*)  d_in[3];
    const float* tboxes  = (const float*)d_in[4];
    const float* tcutin  = (const float*)d_in[5];
    float* out = (float*)d_out;

    int rows = BATCH * NQ;
    softmax_stats_kernel<<<(rows * 32 + 255) / 256, 256>>>(logits);

    dim3 gB((NQ + 255) / 256, NT, BATCH);
    cost_kernel<<<gB, 256>>>(logits, pboxes, pcutin, tlabels, tboxes, tcutin);

    dim3 gT((NQ + 31) / 32, (NT + 31) / 32, BATCH);
    transpose_out_kernel<<<gT, dim3(32, 32)>>>(out);

    lsa_kernel<<<BATCH, LSA_THREADS>>>(out);
}

// round 12
// speedup vs baseline: 7.5931x; 2.9118x over previous
#include <cuda_runtime.h>
#include <math.h>
#include <limits.h>

#define BATCH 32
#define NQ 900
#define NT 300
#define NC 256

__device__ float g_costT[(size_t)BATCH * NT * NQ];   // 34.56 MB
__device__ float g_rowmax[BATCH * NQ];
__device__ float g_rowsum[BATCH * NQ];

// ---------------------------------------------------------------------------
// Kernel A: softmax stats (max + sum of exp) per (b,q) row of logits.
// ---------------------------------------------------------------------------
__global__ void softmax_stats_kernel(const float* __restrict__ logits) {
    int warp = (blockIdx.x * blockDim.x + threadIdx.x) >> 5;
    int lane = threadIdx.x & 31;
    if (warp >= BATCH * NQ) return;
    const float* row = logits + (size_t)warp * NC;
    float vals[8];
    float m = -INFINITY;
#pragma unroll
    for (int i = 0; i < 8; i++) {
        vals[i] = row[lane + 32 * i];
        m = fmaxf(m, vals[i]);
    }
#pragma unroll
    for (int o = 16; o > 0; o >>= 1)
        m = fmaxf(m, __shfl_xor_sync(0xffffffffu, m, o));
    float s = 0.0f;
#pragma unroll
    for (int i = 0; i < 8; i++) s += expf(vals[i] - m);
#pragma unroll
    for (int o = 16; o > 0; o >>= 1)
        s += __shfl_xor_sync(0xffffffffu, s, o);
    if (lane == 0) {
        g_rowmax[warp] = m;
        g_rowsum[warp] = s;
    }
}

// ---------------------------------------------------------------------------
// Kernel B: cost matrix -> g_costT[b][t][q] (coalesced in q).
// ---------------------------------------------------------------------------
__global__ void cost_kernel(const float* __restrict__ logits,
                            const float* __restrict__ pboxes,
                            const float* __restrict__ pcutin,
                            const int*   __restrict__ tlabels,
                            const float* __restrict__ tboxes,
                            const float* __restrict__ tcutin) {
    int q = blockIdx.x * blockDim.x + threadIdx.x;
    int t = blockIdx.y;
    int b = blockIdx.z;
    if (q >= NQ) return;

    float4 pb = reinterpret_cast<const float4*>(pboxes)[b * NQ + q];
    float4 tb = reinterpret_cast<const float4*>(tboxes)[b * NT + t];
    int   lab = tlabels[b * NT + t];

    int rq = b * NQ + q;
    float logit = logits[(size_t)rq * NC + lab];
    float prob  = expf(logit - g_rowmax[rq]) / g_rowsum[rq];

    float l1 = fabsf(pb.x - tb.x) + fabsf(pb.y - tb.y) +
               fabsf(pb.z - tb.z) + fabsf(pb.w - tb.w);

    float area_p = (pb.z - pb.x) * (pb.w - pb.y);
    float area_t = (tb.z - tb.x) * (tb.w - tb.y);

    float ix = fmaxf(fminf(pb.z, tb.z) - fmaxf(pb.x, tb.x), 0.0f);
    float iy = fmaxf(fminf(pb.w, tb.w) - fmaxf(pb.y, tb.y), 0.0f);
    float inter = ix * iy;
    float uni   = area_p + area_t - inter;
    float iou   = inter / uni;

    float ex = fmaxf(fmaxf(pb.z, tb.z) - fminf(pb.x, tb.x), 0.0f);
    float ey = fmaxf(fmaxf(pb.w, tb.w) - fminf(pb.y, tb.y), 0.0f);
    float enc = ex * ey;
    float giou = iou - (enc - uni) / enc;

    float cc = fabsf(pcutin[b * NQ + q] - tcutin[b * NT + t]);

    float cost = 5.0f * l1 - prob - 2.0f * giou + 2.0f * cc;
    g_costT[((size_t)b * NT + t) * NQ + q] = cost;
}

// ---------------------------------------------------------------------------
// Kernel C: transpose g_costT [b][t][q] -> out Cmat [b][q][t] (float32).
// ---------------------------------------------------------------------------
__global__ void transpose_out_kernel(float* __restrict__ out) {
    __shared__ float tile[32][33];
    int b  = blockIdx.z;
    int q0 = blockIdx.x * 32;
    int t0 = blockIdx.y * 32;
    int tx = threadIdx.x, ty = threadIdx.y;

    int q = q0 + tx, t = t0 + ty;
    if (q < NQ && t < NT)
        tile[ty][tx] = g_costT[((size_t)b * NT + t) * NQ + q];
    __syncthreads();
    int q2 = q0 + ty, t2 = t0 + tx;
    if (q2 < NQ && t2 < NT)
        out[((size_t)b * NQ + q2) * NT + t2] = tile[tx][ty];
}

// ---------------------------------------------------------------------------
// Packed-key helpers: 64-bit key = [orderable f32 | column index].
// Unsigned compare on the key == (value, then smallest index) ordering.
// ---------------------------------------------------------------------------
__device__ __forceinline__ unsigned long long pack_key(float f, int j) {
    unsigned u = __float_as_uint(f);
    u = (u & 0x80000000u) ? ~u : (u | 0x80000000u);
    return ((unsigned long long)u << 32) | (unsigned)j;
}
__device__ __forceinline__ float unpack_val(unsigned long long k) {
    unsigned u = (unsigned)(k >> 32);
    u = (u & 0x80000000u) ? (u & 0x7FFFFFFFu) : ~u;
    return __uint_as_float(u);
}
__device__ __forceinline__ unsigned long long umin64(unsigned long long a,
                                                     unsigned long long b) {
    return a < b ? a : b;
}
__device__ __forceinline__ unsigned long long umax64(unsigned long long a,
                                                     unsigned long long b) {
    return a > b ? a : b;
}

// ---------------------------------------------------------------------------
// Kernel D: LAPJV-style LSA.
//   0a: row reduction  u[i] = min_j c[i][j]  (v = 0, dual feasible)
//   0b: greedy assignment on tight (argmin) edges
//   0c: augmenting row reduction (LAPJV) for leftover rows, capped
//   1 : successive-shortest-path Dijkstra for anything still unassigned
// All duals f32; argmin reductions via packed 64-bit keys; 128 threads/block,
// per-thread register state for 8 strided columns.
// ---------------------------------------------------------------------------
#define LSA_THREADS 128
#define LSA_K 8            // 128*8 = 1024 >= 900 columns

__global__ __launch_bounds__(LSA_THREADS, 1) void lsa_kernel(float* __restrict__ out) {
    int b   = blockIdx.x;
    int tid = threadIdx.x;
    int wid = tid >> 5, lane = tid & 31;

    __shared__ float  s_u[NT + 1];
    __shared__ int    s_p[NQ + 1];
    __shared__ int    s_way[NQ + 1];
    __shared__ int    s_rowarg[NT + 1];
    __shared__ unsigned char s_skip[NT + 1];
    __shared__ int    s_list[NT + 1];
    __shared__ int    s_nun;
    __shared__ unsigned long long s_rk[2][4];      // Dijkstra argmin
    __shared__ unsigned long long s_t1[2][4];      // ARR top-2
    __shared__ unsigned long long s_t2[2][4];

    const float* cost = g_costT + (size_t)b * NT * NQ;

    for (int j = tid; j <= NQ; j += LSA_THREADS) s_p[j] = 0;
    __syncthreads();

    // ---- Phase 0a: per-row minima (one warp per row, packed-key reduce) ----
    for (int r = wid; r < NT; r += 4) {
        const float* crow = cost + (size_t)r * NQ;
        unsigned long long bk = ~0ULL;
        for (int j = lane; j < NQ; j += 32)
            bk = umin64(bk, pack_key(__ldg(crow + j), j));
#pragma unroll
        for (int o = 16; o > 0; o >>= 1)
            bk = umin64(bk, __shfl_down_sync(0xffffffffu, bk, o));
        if (lane == 0) {
            s_u[r + 1]      = unpack_val(bk);
            s_rowarg[r + 1] = (int)(bk & 0xFFFFFFFFu) + 1;
        }
    }
    __syncthreads();

    // ---- Phase 0b: greedy assignment on tight edges; build unassigned list ----
    if (tid == 0) {
        s_u[0] = 0.0f;
        int n = 0;
        for (int i = 1; i <= NT; i++) {
            int j = s_rowarg[i];
            if (s_p[j] == 0) { s_p[j] = i; s_skip[i] = 1; }
            else             { s_skip[i] = 0; s_list[n++] = i; }
        }
        s_nun = n;
    }
    __syncthreads();

    float v[LSA_K];
#pragma unroll
    for (int k = 0; k < LSA_K; k++) v[k] = 0.0f;

    // ---- Phase 0c: augmenting row reduction (LAPJV), capped ----
    {
        int par = 0;
        int nun = s_nun;
        int li = 0, cap = 4 * NT;
        int cur = 0;
        while (true) {
            if (cur == 0) {
                if (li >= nun) break;
                cur = s_list[li++];
            }
            if (cap-- <= 0) break;

            // top-2 scan of reduced costs c[cur][j] - v[j]
            const float* crow = cost + (size_t)(cur - 1) * NQ;
            unsigned long long k1 = ~0ULL, k2 = ~0ULL;
#pragma unroll
            for (int k = 0; k < LSA_K; k++) {
                int j = 1 + tid + LSA_THREADS * k;
                if (j <= NQ) {
                    unsigned long long key =
                        pack_key(__ldg(crow + (j - 1)) - v[k], j);
                    if (key < k1)      { k2 = k1; k1 = key; }
                    else if (key < k2) { k2 = key; }
                }
            }
#pragma unroll
            for (int o = 16; o > 0; o >>= 1) {
                unsigned long long o1 = __shfl_down_sync(0xffffffffu, k1, o);
                unsigned long long o2 = __shfl_down_sync(0xffffffffu, k2, o);
                unsigned long long lo = umin64(k1, o1);
                unsigned long long hi = umax64(k1, o1);
                k1 = lo;
                k2 = umin64(hi, umin64(k2, o2));
            }
            if (lane == 0) { s_t1[par][wid] = k1; s_t2[par][wid] = k2; }
            __syncthreads();                        // bar 1

            unsigned long long m1 = s_t1[par][0], m2 = s_t2[par][0];
#pragma unroll
            for (int w = 1; w < 4; w++) {
                unsigned long long a = s_t1[par][w], c2 = s_t2[par][w];
                unsigned long long lo = umin64(m1, a);
                unsigned long long hi = umax64(m1, a);
                m1 = lo;
                m2 = umin64(hi, umin64(m2, c2));
            }
            par ^= 1;

            int   j1   = (int)(m1 & 0xFFFFFFFFu);
            int   j2   = (int)(m2 & 0xFFFFFFFFu);
            float val1 = unpack_val(m1);
            float val2 = unpack_val(m2);
            unsigned hv1 = (unsigned)(m1 >> 32), hv2 = (unsigned)(m2 >> 32);
            bool  strict = hv1 < hv2;               // m1 < m2 (value order)

            int j1f, kdisp;
            if (strict) {
                j1f = j1;
                kdisp = s_p[j1];
            } else {
                int kk = s_p[j1];
                j1f = kk ? j2 : j1;                 // tie: take 2nd col if taken
                kdisp = kk ? s_p[j2] : 0;
            }
            // v[j1] -= (m2 - m1) only in the strict case (keeps feasibility)
            if (strict && (((j1f - 1) & (LSA_THREADS - 1)) == tid))
                v[(j1f - 1) >> 7] -= (val2 - val1);

            __syncthreads();                        // bar 2 (orders s_p update)

            if (tid == 0) {
                s_p[j1f]    = cur;
                s_skip[cur] = 1;
                if (kdisp) s_skip[kdisp] = 0;
                s_u[cur]    = val2;
            }
            cur = kdisp;
        }
        __syncthreads();
    }

    // ---- Phase 1: SSP Dijkstra for remaining rows ----
    int parity = 0;
    for (int i = 1; i <= NT; i++) {
        if (s_skip[i]) continue;

        float minv[LSA_K];
        unsigned usedmask = 0;
#pragma unroll
        for (int k = 0; k < LSA_K; k++) minv[k] = INFINITY;

        int j0 = 0;

        while (true) {
            int   i0  = (j0 == 0) ? i : s_p[j0];
            float ui0 = s_u[i0];
            const float* crow = cost + (size_t)(i0 - 1) * NQ;

            float bval = INFINITY;
            int   bidx = NQ + 1;
#pragma unroll
            for (int k = 0; k < LSA_K; k++) {
                int j = 1 + tid + LSA_THREADS * k;
                if (j <= NQ && !((usedmask >> k) & 1u)) {
                    float cur_ = __ldg(crow + (j - 1)) - ui0 - v[k];
                    if (cur_ < minv[k]) { minv[k] = cur_; s_way[j] = j0; }
                    if (minv[k] < bval) { bval = minv[k]; bidx = j; }
                }
            }

            unsigned long long bk = pack_key(bval, bidx);
#pragma unroll
            for (int o = 16; o > 0; o >>= 1)
                bk = umin64(bk, __shfl_down_sync(0xffffffffu, bk, o));
            if (lane == 0) s_rk[parity][wid] = bk;

            __syncthreads();   // the ONLY barrier per step

            unsigned long long mk = s_rk[parity][0];
#pragma unroll
            for (int w = 1; w < 4; w++) mk = umin64(mk, s_rk[parity][w]);
            parity ^= 1;

            float delta = unpack_val(mk);
            int   j1    = (int)(mk & 0xFFFFFFFFu);

            if (tid == 0) s_u[i] += delta;
#pragma unroll
            for (int k = 0; k < LSA_K; k++) {
                int j = 1 + tid + LSA_THREADS * k;
                if (j <= NQ) {
                    if ((usedmask >> k) & 1u) {
                        v[k] -= delta;
                        s_u[s_p[j]] += delta;
                    } else {
                        minv[k] -= delta;
                    }
                }
            }

            if (((j1 - 1) & (LSA_THREADS - 1)) == tid)
                usedmask |= 1u << ((j1 - 1) >> 7);

            int pj1 = s_p[j1];
            j0 = j1;
            if (pj1 == 0) break;
        }

        __syncthreads();
        if (tid == 0) {
            int jj = j0;
            while (jj) {
                int jp = s_way[jj];
                s_p[jj] = (jp == 0) ? i : s_p[jp];
                jj = jp;
            }
        }
        __syncthreads();
    }

    // ---- emit q_idx and t_idx as float32 ----
    float* qout = out + (size_t)BATCH * NQ * NT + (size_t)b * NT;
    float* tout = out + (size_t)BATCH * NQ * NT + (size_t)BATCH * NT + (size_t)b * NT;
    for (int j = tid + 1; j <= NQ; j += LSA_THREADS) {
        int pi = s_p[j];
        if (pi > 0) qout[pi - 1] = (float)(j - 1);
    }
    for (int t = tid; t < NT; t += LSA_THREADS) tout[t] = (float)t;
}

// ---------------------------------------------------------------------------
extern "C" void kernel_launch(void* const* d_in, const int* in_sizes, int n_in,
                              void* d_out, int out_size) {
    const float* logits  = (const float*)d_in[0];
    const float* pboxes  = (const float*)d_in[1];
    const float* pcutin  = (const float*)d_in[2];
    const int*   tlabels = (const int*)  d_in[3];
    const float* tboxes  = (const float*)d_in[4];
    const float* tcutin  = (const float*)d_in[5];
    float* out = (float*)d_out;

    int rows = BATCH * NQ;
    softmax_stats_kernel<<<(rows * 32 + 255) / 256, 256>>>(logits);

    dim3 gB((NQ + 255) / 256, NT, BATCH);
    cost_kernel<<<gB, 256>>>(logits, pboxes, pcutin, tlabels, tboxes, tcutin);

    dim3 gT((NQ + 31) / 32, (NT + 31) / 32, BATCH);
    transpose_out_kernel<<<gT, dim3(32, 32)>>>(out);

    lsa_kernel<<<BATCH, LSA_THREADS>>>(out);
}

// round 13
// speedup vs baseline: 7.7363x; 1.0189x over previous
#include <cuda_runtime.h>
#include <math.h>
#include <limits.h>

#define BATCH 32
#define NQ 900
#define NT 300
#define NC 256

__device__ float g_costT[(size_t)BATCH * NT * NQ];   // 34.56 MB
__device__ float g_rowmax[BATCH * NQ];
__device__ float g_rowsum[BATCH * NQ];

// ---------------------------------------------------------------------------
// Kernel A: softmax stats (max + sum of exp) per (b,q) row of logits.
// ---------------------------------------------------------------------------
__global__ void softmax_stats_kernel(const float* __restrict__ logits) {
    int warp = (blockIdx.x * blockDim.x + threadIdx.x) >> 5;
    int lane = threadIdx.x & 31;
    if (warp >= BATCH * NQ) return;
    const float* row = logits + (size_t)warp * NC;
    float vals[8];
    float m = -INFINITY;
#pragma unroll
    for (int i = 0; i < 8; i++) {
        vals[i] = row[lane + 32 * i];
        m = fmaxf(m, vals[i]);
    }
#pragma unroll
    for (int o = 16; o > 0; o >>= 1)
        m = fmaxf(m, __shfl_xor_sync(0xffffffffu, m, o));
    float s = 0.0f;
#pragma unroll
    for (int i = 0; i < 8; i++) s += expf(vals[i] - m);
#pragma unroll
    for (int o = 16; o > 0; o >>= 1)
        s += __shfl_xor_sync(0xffffffffu, s, o);
    if (lane == 0) {
        g_rowmax[warp] = m;
        g_rowsum[warp] = s;
    }
}

// ---------------------------------------------------------------------------
// Kernel B (fused): cost matrix -> BOTH g_costT[b][t][q] and out[b][q][t],
// via a 32x32 smem tile per block. Replaces old cost + transpose kernels.
// ---------------------------------------------------------------------------
__global__ void cost_fused_kernel(const float* __restrict__ logits,
                                  const float* __restrict__ pboxes,
                                  const float* __restrict__ pcutin,
                                  const int*   __restrict__ tlabels,
                                  const float* __restrict__ tboxes,
                                  const float* __restrict__ tcutin,
                                  float* __restrict__ out) {
    __shared__ float tile[32][33];
    int b  = blockIdx.z;
    int q0 = blockIdx.x * 32;
    int t0 = blockIdx.y * 32;
    int tx = threadIdx.x, ty = threadIdx.y;   // block (32, 8)

    int q = q0 + tx;
    float4 pb = make_float4(0.f, 0.f, 0.f, 0.f);
    float  pc = 0.f, rmax = 0.f, rsum = 1.f;
    if (q < NQ) {
        pb   = reinterpret_cast<const float4*>(pboxes)[b * NQ + q];
        pc   = pcutin[b * NQ + q];
        rmax = g_rowmax[b * NQ + q];
        rsum = g_rowsum[b * NQ + q];
    }

#pragma unroll
    for (int s = 0; s < 4; s++) {
        int t = t0 + ty + 8 * s;
        float cval = 0.0f;
        if (q < NQ && t < NT) {
            float4 tb = reinterpret_cast<const float4*>(tboxes)[b * NT + t];
            int   lab = tlabels[b * NT + t];

            float logit = logits[((size_t)(b * NQ + q)) * NC + lab];
            float prob  = expf(logit - rmax) / rsum;

            float l1 = fabsf(pb.x - tb.x) + fabsf(pb.y - tb.y) +
                       fabsf(pb.z - tb.z) + fabsf(pb.w - tb.w);

            float area_p = (pb.z - pb.x) * (pb.w - pb.y);
            float area_t = (tb.z - tb.x) * (tb.w - tb.y);

            float ix = fmaxf(fminf(pb.z, tb.z) - fmaxf(pb.x, tb.x), 0.0f);
            float iy = fmaxf(fminf(pb.w, tb.w) - fmaxf(pb.y, tb.y), 0.0f);
            float inter = ix * iy;
            float uni   = area_p + area_t - inter;
            float iou   = inter / uni;

            float ex = fmaxf(fmaxf(pb.z, tb.z) - fminf(pb.x, tb.x), 0.0f);
            float ey = fmaxf(fmaxf(pb.w, tb.w) - fminf(pb.y, tb.y), 0.0f);
            float enc = ex * ey;
            float giou = iou - (enc - uni) / enc;

            float cc = fabsf(pc - tcutin[b * NT + t]);

            cval = 5.0f * l1 - prob - 2.0f * giou + 2.0f * cc;
            g_costT[((size_t)b * NT + t) * NQ + q] = cval;   // q-coalesced
        }
        tile[ty + 8 * s][tx] = cval;                          // tile[t][q]
    }
    __syncthreads();

#pragma unroll
    for (int s = 0; s < 4; s++) {
        int q2 = q0 + ty + 8 * s;
        int t2 = t0 + tx;
        if (q2 < NQ && t2 < NT)
            out[((size_t)b * NQ + q2) * NT + t2] = tile[tx][ty + 8 * s];  // t-coalesced
    }
}

// ---------------------------------------------------------------------------
// Packed-key helpers: 64-bit key = [orderable f32 | column index].
// Unsigned compare on the key == (value, then smallest index) ordering.
// ---------------------------------------------------------------------------
__device__ __forceinline__ unsigned long long pack_key(float f, int j) {
    unsigned u = __float_as_uint(f);
    u = (u & 0x80000000u) ? ~u : (u | 0x80000000u);
    return ((unsigned long long)u << 32) | (unsigned)j;
}
__device__ __forceinline__ float unpack_val(unsigned long long k) {
    unsigned u = (unsigned)(k >> 32);
    u = (u & 0x80000000u) ? (u & 0x7FFFFFFFu) : ~u;
    return __uint_as_float(u);
}
__device__ __forceinline__ unsigned long long umin64(unsigned long long a,
                                                     unsigned long long b) {
    return a < b ? a : b;
}
__device__ __forceinline__ unsigned long long umax64(unsigned long long a,
                                                     unsigned long long b) {
    return a > b ? a : b;
}

// ---------------------------------------------------------------------------
// Kernel D: LAPJV-style LSA (row reduction + greedy + ARR + SSP Dijkstra).
// Phase 1 is software-pipelined: the next row's cost values are prefetched
// into registers as soon as j1 is known, hiding the L2 latency behind the
// dual update + barrier.
// ---------------------------------------------------------------------------
#define LSA_THREADS 128
#define LSA_K 8            // 128*8 = 1024 >= 900 columns

__global__ __launch_bounds__(LSA_THREADS, 1) void lsa_kernel(float* __restrict__ out) {
    int b   = blockIdx.x;
    int tid = threadIdx.x;
    int wid = tid >> 5, lane = tid & 31;

    __shared__ float  s_u[NT + 1];
    __shared__ int    s_p[NQ + 1];
    __shared__ int    s_way[NQ + 1];
    __shared__ int    s_rowarg[NT + 1];
    __shared__ unsigned char s_skip[NT + 1];
    __shared__ int    s_list[NT + 1];
    __shared__ int    s_nun;
    __shared__ unsigned long long s_rk[2][4];      // Dijkstra argmin
    __shared__ unsigned long long s_t1[2][4];      // ARR top-2
    __shared__ unsigned long long s_t2[2][4];

    const float* cost = g_costT + (size_t)b * NT * NQ;

    for (int j = tid; j <= NQ; j += LSA_THREADS) s_p[j] = 0;
    __syncthreads();

    // ---- Phase 0a: per-row minima (one warp per row, packed-key reduce) ----
    for (int r = wid; r < NT; r += 4) {
        const float* crow = cost + (size_t)r * NQ;
        unsigned long long bk = ~0ULL;
        for (int j = lane; j < NQ; j += 32)
            bk = umin64(bk, pack_key(__ldg(crow + j), j));
#pragma unroll
        for (int o = 16; o > 0; o >>= 1)
            bk = umin64(bk, __shfl_down_sync(0xffffffffu, bk, o));
        if (lane == 0) {
            s_u[r + 1]      = unpack_val(bk);
            s_rowarg[r + 1] = (int)(bk & 0xFFFFFFFFu) + 1;
        }
    }
    __syncthreads();

    // ---- Phase 0b: greedy assignment on tight edges; build unassigned list ----
    if (tid == 0) {
        s_u[0] = 0.0f;
        int n = 0;
        for (int i = 1; i <= NT; i++) {
            int j = s_rowarg[i];
            if (s_p[j] == 0) { s_p[j] = i; s_skip[i] = 1; }
            else             { s_skip[i] = 0; s_list[n++] = i; }
        }
        s_nun = n;
    }
    __syncthreads();

    float v[LSA_K];
#pragma unroll
    for (int k = 0; k < LSA_K; k++) v[k] = 0.0f;

    // ---- Phase 0c: augmenting row reduction (LAPJV), capped ----
    {
        int par = 0;
        int nun = s_nun;
        int li = 0, cap = 4 * NT;
        int cur = 0;
        while (true) {
            if (cur == 0) {
                if (li >= nun) break;
                cur = s_list[li++];
            }
            if (cap-- <= 0) break;

            // top-2 scan of reduced costs c[cur][j] - v[j]
            const float* crow = cost + (size_t)(cur - 1) * NQ;
            unsigned long long k1 = ~0ULL, k2 = ~0ULL;
#pragma unroll
            for (int k = 0; k < LSA_K; k++) {
                int j = 1 + tid + LSA_THREADS * k;
                if (j <= NQ) {
                    unsigned long long key =
                        pack_key(__ldg(crow + (j - 1)) - v[k], j);
                    if (key < k1)      { k2 = k1; k1 = key; }
                    else if (key < k2) { k2 = key; }
                }
            }
#pragma unroll
            for (int o = 16; o > 0; o >>= 1) {
                unsigned long long o1 = __shfl_down_sync(0xffffffffu, k1, o);
                unsigned long long o2 = __shfl_down_sync(0xffffffffu, k2, o);
                unsigned long long lo = umin64(k1, o1);
                unsigned long long hi = umax64(k1, o1);
                k1 = lo;
                k2 = umin64(hi, umin64(k2, o2));
            }
            if (lane == 0) { s_t1[par][wid] = k1; s_t2[par][wid] = k2; }
            __syncthreads();                        // bar 1

            unsigned long long m1 = s_t1[par][0], m2 = s_t2[par][0];
#pragma unroll
            for (int w = 1; w < 4; w++) {
                unsigned long long a = s_t1[par][w], c2 = s_t2[par][w];
                unsigned long long lo = umin64(m1, a);
                unsigned long long hi = umax64(m1, a);
                m1 = lo;
                m2 = umin64(hi, umin64(m2, c2));
            }
            par ^= 1;

            int   j1   = (int)(m1 & 0xFFFFFFFFu);
            int   j2   = (int)(m2 & 0xFFFFFFFFu);
            float val1 = unpack_val(m1);
            float val2 = unpack_val(m2);
            unsigned hv1 = (unsigned)(m1 >> 32), hv2 = (unsigned)(m2 >> 32);
            bool  strict = hv1 < hv2;               // m1 < m2 (value order)

            int j1f, kdisp;
            if (strict) {
                j1f = j1;
                kdisp = s_p[j1];
            } else {
                int kk = s_p[j1];
                j1f = kk ? j2 : j1;                 // tie: take 2nd col if taken
                kdisp = kk ? s_p[j2] : 0;
            }
            // v[j1] -= (m2 - m1) only in the strict case (keeps feasibility)
            if (strict && (((j1f - 1) & (LSA_THREADS - 1)) == tid))
                v[(j1f - 1) >> 7] -= (val2 - val1);

            __syncthreads();                        // bar 2 (orders s_p update)

            if (tid == 0) {
                s_p[j1f]    = cur;
                s_skip[cur] = 1;
                if (kdisp) s_skip[kdisp] = 0;
                s_u[cur]    = val2;
            }
            cur = kdisp;
        }
        __syncthreads();
    }

    // ---- Phase 1: SSP Dijkstra for remaining rows (pipelined row loads) ----
    int parity = 0;
    for (int i = 1; i <= NT; i++) {
        if (s_skip[i]) continue;

        float minv[LSA_K];
        unsigned usedmask = 0;
#pragma unroll
        for (int k = 0; k < LSA_K; k++) minv[k] = INFINITY;

        int j0 = 0;
        int i0 = i;

        // prefetch row i0 into registers
        float pre[LSA_K];
#pragma unroll
        for (int k = 0; k < LSA_K; k++) {
            int j = 1 + tid + LSA_THREADS * k;
            pre[k] = (j <= NQ) ? __ldg(cost + (size_t)(i0 - 1) * NQ + (j - 1)) : 0.0f;
        }

        while (true) {
            float ui0 = s_u[i0];

            float bval = INFINITY;
            int   bidx = NQ + 1;
#pragma unroll
            for (int k = 0; k < LSA_K; k++) {
                int j = 1 + tid + LSA_THREADS * k;
                if (j <= NQ && !((usedmask >> k) & 1u)) {
                    float cur_ = pre[k] - ui0 - v[k];
                    if (cur_ < minv[k]) { minv[k] = cur_; s_way[j] = j0; }
                    if (minv[k] < bval) { bval = minv[k]; bidx = j; }
                }
            }

            unsigned long long bk = pack_key(bval, bidx);
#pragma unroll
            for (int o = 16; o > 0; o >>= 1)
                bk = umin64(bk, __shfl_down_sync(0xffffffffu, bk, o));
            if (lane == 0) s_rk[parity][wid] = bk;

            __syncthreads();   // the ONLY barrier per step

            unsigned long long mk = s_rk[parity][0];
#pragma unroll
            for (int w = 1; w < 4; w++) mk = umin64(mk, s_rk[parity][w]);
            parity ^= 1;

            float delta = unpack_val(mk);
            int   j1    = (int)(mk & 0xFFFFFFFFu);
            int   pj1   = s_p[j1];          // next row (0 => free col, done)

            // prefetch next row NOW — L2 latency overlaps the dual update
            if (pj1 != 0) {
#pragma unroll
                for (int k = 0; k < LSA_K; k++) {
                    int j = 1 + tid + LSA_THREADS * k;
                    pre[k] = (j <= NQ) ? __ldg(cost + (size_t)(pj1 - 1) * NQ + (j - 1)) : 0.0f;
                }
            }

            if (tid == 0) s_u[i] += delta;
#pragma unroll
            for (int k = 0; k < LSA_K; k++) {
                int j = 1 + tid + LSA_THREADS * k;
                if (j <= NQ) {
                    if ((usedmask >> k) & 1u) {
                        v[k] -= delta;
                        s_u[s_p[j]] += delta;
                    } else {
                        minv[k] -= delta;
                    }
                }
            }

            if (((j1 - 1) & (LSA_THREADS - 1)) == tid)
                usedmask |= 1u << ((j1 - 1) >> 7);

            j0 = j1;
            i0 = pj1;
            if (pj1 == 0) break;
        }

        __syncthreads();
        if (tid == 0) {
            int jj = j0;
            while (jj) {
                int jp = s_way[jj];
                s_p[jj] = (jp == 0) ? i : s_p[jp];
                jj = jp;
            }
        }
        __syncthreads();
    }

    // ---- emit q_idx and t_idx as float32 ----
    float* qout = out + (size_t)BATCH * NQ * NT + (size_t)b * NT;
    float* tout = out + (size_t)BATCH * NQ * NT + (size_t)BATCH * NT + (size_t)b * NT;
    for (int j = tid + 1; j <= NQ; j += LSA_THREADS) {
        int pi = s_p[j];
        if (pi > 0) qout[pi - 1] = (float)(j - 1);
    }
    for (int t = tid; t < NT; t += LSA_THREADS) tout[t] = (float)t;
}

// ---------------------------------------------------------------------------
extern "C" void kernel_launch(void* const* d_in, const int* in_sizes, int n_in,
                              void* d_out, int out_size) {
    const float* logits  = (const float*)d_in[0];
    const float* pboxes  = (const float*)d_in[1];
    const float* pcutin  = (const float*)d_in[2];
    const int*   tlabels = (const int*)  d_in[3];
    const float* tboxes  = (const float*)d_in[4];
    const float* tcutin  = (const float*)d_in[5];
    float* out = (float*)d_out;

    int rows = BATCH * NQ;
    softmax_stats_kernel<<<(rows * 32 + 255) / 256, 256>>>(logits);

    dim3 gB((NQ + 31) / 32, (NT + 31) / 32, BATCH);
    cost_fused_kernel<<<gB, dim3(32, 8)>>>(logits, pboxes, pcutin,
                                           tlabels, tboxes, tcutin, out);

    lsa_kernel<<<BATCH, LSA_THREADS>>>(out);
}